// round 15
// baseline (speedup 1.0000x reference)
#include <cuda_runtime.h>
#include <cuda_bf16.h>

// SkipGram negative-sampling loss — FINAL (converged): fused, register-lean,
// software-pipelined (depth 2). Triple-benched at 88.13/88.35/88.83us —
// ~95% of the path-independent LTS throughput cap for the compulsory ~946MB
// of gather traffic. Verified equal-or-worse alternatives: reg-batched loads
// (R4), max-occupancy (R7), partial prefetch (R10), shfl-distributed indices
// (R11), 512-thread blocks (R13).
// Inputs (metadata order):
//   d_in[0] u_weight  [VOCAB, 300] f32
//   d_in[1] v_weight  [VOCAB, 300] f32
//   d_in[2] pos_u     [B] i32
//   d_in[3] pos_v     [B] i32
//   d_in[4] neg_v     [B, 10] i32
// Output: scalar f32 mean loss.

#define DIM   300
#define KNEG  10
#define NROWS 11
#define WARPS_PER_BLOCK 8
#define BLOCK_THREADS (WARPS_PER_BLOCK * 32)

// Packed accumulator: bits[0..49] fixed-point loss sum (scale 2^26),
//                     bits[50..63] block-arrival counter (unit 2^50).
// Integer adds are order-independent -> bit-deterministic across replays.
__device__ unsigned long long g_acc = 0ull;

#define FIX_SCALE  67108864.0f          /* 2^26 */
#define FIX_INV    (1.0 / 67108864.0)   /* 2^-26 */
#define CNT_UNIT   (1ull << 50)
#define SUM_MASK   (CNT_UNIT - 1ull)

__device__ __forceinline__ float4 ld_v4_pol(const float4* p, unsigned long long pol) {
    float4 r;
    asm volatile("ld.global.nc.L2::cache_hint.v4.f32 {%0,%1,%2,%3}, [%4], %5;"
                 : "=f"(r.x), "=f"(r.y), "=f"(r.z), "=f"(r.w)
                 : "l"(p), "l"(pol));
    return r;
}

__global__ void __launch_bounds__(BLOCK_THREADS, 5)   // reg ceiling 51; compiles to 48
sg_fused_kernel(const float* __restrict__ uw,
                const float* __restrict__ vw,
                const int*  __restrict__ pos_u,
                const int*  __restrict__ pos_v,
                const int*  __restrict__ neg_v,
                float* __restrict__ out,
                int B, float inv_B)
{
    const int lane = threadIdx.x & 31;
    const int wib  = threadIdx.x >> 5;
    const int b    = blockIdx.x * WARPS_PER_BLOCK + wib;

    unsigned long long pol_keep, pol_stream;
    asm("createpolicy.fractional.L2::evict_last.b64  %0, 1.0;" : "=l"(pol_keep));
    asm("createpolicy.fractional.L2::evict_first.b64 %0, 1.0;" : "=l"(pol_stream));

    float warp_loss = 0.0f;

    if (b < B) {
        // ---- u row: 75 float4 across the warp (streaming; low reuse) ----
        const size_t u_idx = (size_t)__ldg(&pos_u[b]);
        const float4* ur = reinterpret_cast<const float4*>(uw + u_idx * DIM);
        float4 u0 = ld_v4_pol(&ur[lane], pol_stream);
        float4 u1 = ld_v4_pol(&ur[lane + 32], pol_stream);
        float4 u2 = make_float4(0.f, 0.f, 0.f, 0.f);
        const bool tail = (lane < 11);
        if (tail) u2 = ld_v4_pol(&ur[lane + 64], pol_stream);

        float loss = 0.0f;

        // ---- pipeline prologue: load row 0 (pos_v) ----
        const float4* vr = reinterpret_cast<const float4*>(
            vw + (size_t)__ldg(&pos_v[b]) * DIM);
        float4 v0 = ld_v4_pol(&vr[lane], pol_keep);
        float4 v1 = ld_v4_pol(&vr[lane + 32], pol_keep);
        float4 v2 = make_float4(0.f, 0.f, 0.f, 0.f);
        if (tail) v2 = ld_v4_pol(&vr[lane + 64], pol_keep);

        #pragma unroll
        for (int k = 0; k < NROWS; k++) {
            // ---- prefetch row k+1 while row k's data is in flight / computing ----
            // (index loads are address-independent; ptxas hoists them to the top)
            float4 n0, n1, n2;
            const float4* nr = vr;
            if (k < NROWS - 1) {
                nr = reinterpret_cast<const float4*>(
                    vw + (size_t)__ldg(&neg_v[b * KNEG + k]) * DIM);
                n0 = ld_v4_pol(&nr[lane], pol_keep);
                n1 = ld_v4_pol(&nr[lane + 32], pol_keep);
                n2 = make_float4(0.f, 0.f, 0.f, 0.f);
                if (tail) n2 = ld_v4_pol(&nr[lane + 64], pol_keep);
            }

            // ---- compute row k ----
            float a = 0.f;
            a = fmaf(u0.x, v0.x, a);
            a = fmaf(u0.y, v0.y, a);
            a = fmaf(u0.z, v0.z, a);
            a = fmaf(u0.w, v0.w, a);
            a = fmaf(u1.x, v1.x, a);
            a = fmaf(u1.y, v1.y, a);
            a = fmaf(u1.z, v1.z, a);
            a = fmaf(u1.w, v1.w, a);
            if (tail) {
                a = fmaf(u2.x, v2.x, a);
                a = fmaf(u2.y, v2.y, a);
                a = fmaf(u2.z, v2.z, a);
                a = fmaf(u2.w, v2.w, a);
            }
            // full xor-butterfly: all lanes end with the row sum
            a += __shfl_xor_sync(0xffffffffu, a, 16);
            a += __shfl_xor_sync(0xffffffffu, a, 8);
            a += __shfl_xor_sync(0xffffffffu, a, 4);
            a += __shfl_xor_sync(0xffffffffu, a, 2);
            a += __shfl_xor_sync(0xffffffffu, a, 1);

            float s = fminf(fmaxf(a, -10.f), 10.f);
            // k==0: -log_sigmoid(s) = log(1+exp(-s)); else: -log_sigmoid(-s) = log(1+exp(s))
            float e = __expf((k == 0) ? -s : s);
            loss += __logf(1.0f + e);

            // ---- rotate pipeline ----
            if (k < NROWS - 1) { vr = nr; v0 = n0; v1 = n1; v2 = n2; }
        }
        warp_loss = loss;   // identical on all lanes
    }

    // ---- block partial (deterministic fixed order within block) ----
    __shared__ float ws[WARPS_PER_BLOCK];
    if (lane == 0) ws[wib] = warp_loss;
    __syncthreads();

    if (threadIdx.x == 0) {
        float s = 0.f;
        #pragma unroll
        for (int i = 0; i < WARPS_PER_BLOCK; i++) s += ws[i];

        // pack fixed-point partial + arrival count: one atomic, no fences
        unsigned long long fixed = (unsigned long long)(double)(s * FIX_SCALE);
        unsigned long long old = atomicAdd(&g_acc, fixed + CNT_UNIT);

        if ((old >> 50) == (unsigned long long)(gridDim.x - 1)) {
            unsigned long long total = (old & SUM_MASK) + fixed;
            out[0] = (float)((double)total * FIX_INV * (double)inv_B);
            g_acc = 0ull;                 // reset for next graph replay
        }
    }
}

extern "C" void kernel_launch(void* const* d_in, const int* in_sizes, int n_in,
                              void* d_out, int out_size)
{
    const float* uw    = (const float*)d_in[0];
    const float* vw    = (const float*)d_in[1];
    const int*   pos_u = (const int*)d_in[2];
    const int*   pos_v = (const int*)d_in[3];
    const int*   neg_v = (const int*)d_in[4];
    float* out = (float*)d_out;

    const int B = in_sizes[2];
    const int nblocks = (B + WARPS_PER_BLOCK - 1) / WARPS_PER_BLOCK;  // 8192

    sg_fused_kernel<<<nblocks, BLOCK_THREADS>>>(uw, vw, pos_u, pos_v, neg_v,
                                                out, B, 1.0f / (float)B);
}

// round 16
// speedup vs baseline: 1.0385x; 1.0385x over previous
#include <cuda_runtime.h>
#include <cuda_bf16.h>

// SkipGram negative-sampling loss — fused, register-lean, software-pipelined (depth 2).
// Converged family (88.1-88.8us, ~95% of path-independent LTS cap on ~946MB compulsory
// gather traffic). This round: 128-thread blocks (finer scheduling granularity, same
// 51-reg ceiling via min_blocks=10); hot loop unchanged.
// Inputs (metadata order):
//   d_in[0] u_weight  [VOCAB, 300] f32
//   d_in[1] v_weight  [VOCAB, 300] f32
//   d_in[2] pos_u     [B] i32
//   d_in[3] pos_v     [B] i32
//   d_in[4] neg_v     [B, 10] i32
// Output: scalar f32 mean loss.

#define DIM   300
#define KNEG  10
#define NROWS 11
#define WARPS_PER_BLOCK 4
#define BLOCK_THREADS (WARPS_PER_BLOCK * 32)

// Packed accumulator: bits[0..49] fixed-point loss sum (scale 2^26),
//                     bits[50..63] block-arrival counter (unit 2^50).
// Integer adds are order-independent -> bit-deterministic across replays.
// 16384 blocks: max observed 'old' counter = 16383 (fits 14 bits); final wrap
// carries out of bit63 harmlessly and the accumulator is reset each launch.
__device__ unsigned long long g_acc = 0ull;

#define FIX_SCALE  67108864.0f          /* 2^26 */
#define FIX_INV    (1.0 / 67108864.0)   /* 2^-26 */
#define CNT_UNIT   (1ull << 50)
#define SUM_MASK   (CNT_UNIT - 1ull)

__device__ __forceinline__ float4 ld_v4_pol(const float4* p, unsigned long long pol) {
    float4 r;
    asm volatile("ld.global.nc.L2::cache_hint.v4.f32 {%0,%1,%2,%3}, [%4], %5;"
                 : "=f"(r.x), "=f"(r.y), "=f"(r.z), "=f"(r.w)
                 : "l"(p), "l"(pol));
    return r;
}

__global__ void __launch_bounds__(BLOCK_THREADS, 10)  // 51-reg ceiling (same as 256x5)
sg_fused_kernel(const float* __restrict__ uw,
                const float* __restrict__ vw,
                const int*  __restrict__ pos_u,
                const int*  __restrict__ pos_v,
                const int*  __restrict__ neg_v,
                float* __restrict__ out,
                int B, float inv_B)
{
    const int lane = threadIdx.x & 31;
    const int wib  = threadIdx.x >> 5;
    const int b    = blockIdx.x * WARPS_PER_BLOCK + wib;

    unsigned long long pol_keep, pol_stream;
    asm("createpolicy.fractional.L2::evict_last.b64  %0, 1.0;" : "=l"(pol_keep));
    asm("createpolicy.fractional.L2::evict_first.b64 %0, 1.0;" : "=l"(pol_stream));

    float warp_loss = 0.0f;

    if (b < B) {
        // ---- u row: 75 float4 across the warp (streaming; low reuse) ----
        const size_t u_idx = (size_t)__ldg(&pos_u[b]);
        const float4* ur = reinterpret_cast<const float4*>(uw + u_idx * DIM);
        float4 u0 = ld_v4_pol(&ur[lane], pol_stream);
        float4 u1 = ld_v4_pol(&ur[lane + 32], pol_stream);
        float4 u2 = make_float4(0.f, 0.f, 0.f, 0.f);
        const bool tail = (lane < 11);
        if (tail) u2 = ld_v4_pol(&ur[lane + 64], pol_stream);

        float loss = 0.0f;

        // ---- pipeline prologue: load row 0 (pos_v) ----
        const float4* vr = reinterpret_cast<const float4*>(
            vw + (size_t)__ldg(&pos_v[b]) * DIM);
        float4 v0 = ld_v4_pol(&vr[lane], pol_keep);
        float4 v1 = ld_v4_pol(&vr[lane + 32], pol_keep);
        float4 v2 = make_float4(0.f, 0.f, 0.f, 0.f);
        if (tail) v2 = ld_v4_pol(&vr[lane + 64], pol_keep);

        #pragma unroll
        for (int k = 0; k < NROWS; k++) {
            // ---- prefetch row k+1 while row k's data is in flight / computing ----
            // (index loads are address-independent; ptxas hoists them to the top)
            float4 n0, n1, n2;
            const float4* nr = vr;
            if (k < NROWS - 1) {
                nr = reinterpret_cast<const float4*>(
                    vw + (size_t)__ldg(&neg_v[b * KNEG + k]) * DIM);
                n0 = ld_v4_pol(&nr[lane], pol_keep);
                n1 = ld_v4_pol(&nr[lane + 32], pol_keep);
                n2 = make_float4(0.f, 0.f, 0.f, 0.f);
                if (tail) n2 = ld_v4_pol(&nr[lane + 64], pol_keep);
            }

            // ---- compute row k ----
            float a = 0.f;
            a = fmaf(u0.x, v0.x, a);
            a = fmaf(u0.y, v0.y, a);
            a = fmaf(u0.z, v0.z, a);
            a = fmaf(u0.w, v0.w, a);
            a = fmaf(u1.x, v1.x, a);
            a = fmaf(u1.y, v1.y, a);
            a = fmaf(u1.z, v1.z, a);
            a = fmaf(u1.w, v1.w, a);
            if (tail) {
                a = fmaf(u2.x, v2.x, a);
                a = fmaf(u2.y, v2.y, a);
                a = fmaf(u2.z, v2.z, a);
                a = fmaf(u2.w, v2.w, a);
            }
            // full xor-butterfly: all lanes end with the row sum
            a += __shfl_xor_sync(0xffffffffu, a, 16);
            a += __shfl_xor_sync(0xffffffffu, a, 8);
            a += __shfl_xor_sync(0xffffffffu, a, 4);
            a += __shfl_xor_sync(0xffffffffu, a, 2);
            a += __shfl_xor_sync(0xffffffffu, a, 1);

            float s = fminf(fmaxf(a, -10.f), 10.f);
            // k==0: -log_sigmoid(s) = log(1+exp(-s)); else: -log_sigmoid(-s) = log(1+exp(s))
            float e = __expf((k == 0) ? -s : s);
            loss += __logf(1.0f + e);

            // ---- rotate pipeline ----
            if (k < NROWS - 1) { vr = nr; v0 = n0; v1 = n1; v2 = n2; }
        }
        warp_loss = loss;   // identical on all lanes
    }

    // ---- block partial (deterministic fixed order within block) ----
    __shared__ float ws[WARPS_PER_BLOCK];
    if (lane == 0) ws[wib] = warp_loss;
    __syncthreads();

    if (threadIdx.x == 0) {
        float s = 0.f;
        #pragma unroll
        for (int i = 0; i < WARPS_PER_BLOCK; i++) s += ws[i];

        // pack fixed-point partial + arrival count: one atomic, no fences
        unsigned long long fixed = (unsigned long long)(double)(s * FIX_SCALE);
        unsigned long long old = atomicAdd(&g_acc, fixed + CNT_UNIT);

        if ((old >> 50) == (unsigned long long)(gridDim.x - 1)) {
            unsigned long long total = (old & SUM_MASK) + fixed;
            out[0] = (float)((double)total * FIX_INV * (double)inv_B);
            g_acc = 0ull;                 // reset for next graph replay
        }
    }
}

extern "C" void kernel_launch(void* const* d_in, const int* in_sizes, int n_in,
                              void* d_out, int out_size)
{
    const float* uw    = (const float*)d_in[0];
    const float* vw    = (const float*)d_in[1];
    const int*   pos_u = (const int*)d_in[2];
    const int*   pos_v = (const int*)d_in[3];
    const int*   neg_v = (const int*)d_in[4];
    float* out = (float*)d_out;

    const int B = in_sizes[2];
    const int nblocks = (B + WARPS_PER_BLOCK - 1) / WARPS_PER_BLOCK;  // 16384

    sg_fused_kernel<<<nblocks, BLOCK_THREADS>>>(uw, vw, pos_u, pos_v, neg_v,
                                                out, B, 1.0f / (float)B);
}